// round 1
// baseline (speedup 1.0000x reference)
#include <cuda_runtime.h>
#include <math.h>

#define NMAX   8192
#define TILE   2048
#define TPB    256
#define RPC    32      // rows per CTA (TPB/8)

__device__ float4 g_table[NMAX];   // (yt, u = yp*log2e, -u*yt, yp)
__device__ float  g_ytmin;
__device__ float  g_total;
__device__ float  g_count;

// ---------------- Kernel A: prep table, global min, zero accumulators ------
__global__ void __launch_bounds__(1024) pro_prep(const float* __restrict__ pred,
                                                 const float* __restrict__ ytrue,
                                                 int n, int padn)
{
    const float INV_T = 20.0f;               // 1 / 0.05
    const float LOG2E = 1.4426950408889634f;
    int t = threadIdx.x;
    float mn = 1e30f;
    for (int i = t; i < padn; i += 1024) {
        if (i < n) {
            float y  = ytrue[i];
            float yp = pred[i] * INV_T;
            float u  = yp * LOG2E;
            g_table[i] = make_float4(y, u, -u * y, yp);
            mn = fminf(mn, y);
        } else {
            // padding: yt=+huge so the predicate (ytj < ytk-eps) never fires
            g_table[i] = make_float4(1e30f, 0.0f, 0.0f, 0.0f);
        }
    }
    // reduce min across block
    #pragma unroll
    for (int o = 16; o; o >>= 1) mn = fminf(mn, __shfl_xor_sync(0xffffffffu, mn, o));
    __shared__ float smn[32];
    if ((t & 31) == 0) smn[t >> 5] = mn;
    __syncthreads();
    if (t < 32) {
        float v = (t < (int)(blockDim.x >> 5)) ? smn[t] : 1e30f;
        #pragma unroll
        for (int o = 16; o; o >>= 1) v = fminf(v, __shfl_xor_sync(0xffffffffu, v, o));
        if (t == 0) { g_ytmin = v; g_total = 0.0f; g_count = 0.0f; }
    }
}

// ---------------- Kernel B: O(N^2) pairwise pass ---------------------------
__global__ void __launch_bounds__(TPB) pro_main(int n, int padn)
{
    __shared__ float4 sm[TILE];            // 32 KB
    __shared__ float  s_tot, s_cnt;

    const float MAGIC = 12582912.0f;       // 1.5 * 2^23
    const float C1 = 0.6931471805599453f;
    const float C2 = 0.24022650695910072f;
    const float C3 = 0.0555041086648216f;
    const float C4 = 0.009618129107628477f;
    const float C5 = 0.0013333558146428443f;
    const float C6 = 1.5403530393381609e-4f;

    int t  = threadIdx.x;
    int tx = t & 7;        // 8 threads stride the j dimension
    int ty = t >> 3;       // row within CTA
    int k  = blockIdx.x * RPC + ty;

    if (t == 0) { s_tot = 0.0f; s_cnt = 0.0f; }

    float ytk, ypk;
    if (k < n) { float4 rd = g_table[k]; ytk = rd.x; ypk = rd.w; }
    else       { ytk = -1e30f; ypk = 0.0f; }
    float ytk_eps = ytk - 1e-8f;

    float s = 0.0f;

    for (int base = 0; base < padn; base += TILE) {
        __syncthreads();
        #pragma unroll
        for (int i = t; i < TILE; i += TPB) sm[i] = g_table[base + i];
        __syncthreads();

        #pragma unroll 4
        for (int i = tx; i < TILE; i += 8) {
            float4 e = sm[i];                         // (ytj, u, -u*ytj, ypj)
            float tt = fmaf(ytk, e.y, e.z);           // log2e * ypj * (ytk - ytj)
            // exp2(tt) via magic-round + degree-6 Taylor + exponent-bit add
            float r  = tt + MAGIC;
            float f  = tt - (r - MAGIC);              // f in [-0.5, 0.5]
            float p  = fmaf(f, C6, C5);
            p = fmaf(f, p, C4);
            p = fmaf(f, p, C3);
            p = fmaf(f, p, C2);
            p = fmaf(f, p, C1);
            p = fmaf(f, p, 1.0f);
            int   sc = __float_as_int(r) << 23;       // i*2^23 (magic bits shift out)
            float ev = __int_as_float(__float_as_int(p) + sc);
            if (e.x < ytk_eps) s += ev;               // masked accumulate
        }
    }

    // reduce the 8 per-row partials (lanes tx=0..7 within each ty group)
    s += __shfl_xor_sync(0xffffffffu, s, 1);
    s += __shfl_xor_sync(0xffffffffu, s, 2);
    s += __shfl_xor_sync(0xffffffffu, s, 4);

    if (tx == 0 && k < n) {
        float d = ytk - g_ytmin;
        if (d > 1e-8f) {
            float lp  = ypk * d;                       // positive logit
            float lpr = lp - logf(expf(lp) + s);       // log_softmax[0], no m needed
            atomicAdd(&s_tot, lpr);
            atomicAdd(&s_cnt, 1.0f);
        }
    }
    __syncthreads();
    if (t == 0) {
        atomicAdd(&g_total, s_tot);
        atomicAdd(&g_count, s_cnt);
    }
}

// ---------------- Kernel C: finalize ---------------------------------------
__global__ void pro_finish(float* out)
{
    float c = g_count;
    out[0] = (c > 0.0f) ? (-g_total / c) : 0.0f;
}

// ---------------- Launch ----------------------------------------------------
extern "C" void kernel_launch(void* const* d_in, const int* in_sizes, int n_in,
                              void* d_out, int out_size)
{
    const float* pred = (const float*)d_in[0];   // predict_similarity
    const float* yt   = (const float*)d_in[1];   // true_similarity
    int n = in_sizes[0];
    if (n > NMAX) n = NMAX;                      // capacity guard (dataset: N=8192)
    int padn = ((n + TILE - 1) / TILE) * TILE;
    if (padn > NMAX) padn = NMAX;

    pro_prep<<<1, 1024>>>(pred, yt, n, padn);
    int grid = (n + RPC - 1) / RPC;
    pro_main<<<grid, TPB>>>(n, padn);
    pro_finish<<<1, 1>>>((float*)d_out);
}